// round 6
// baseline (speedup 1.0000x reference)
#include <cuda_runtime.h>
#include <cstddef>

#define B_ROWS  65536
#define C_CODES 4096
#define DIM     128

// Scratch (no allocations allowed)
__device__ float g_cnorm[C_CODES];
__device__ int   g_index[B_ROWS];
__device__ float g_partial[512];

// ---------------------------------------------------------------------------
// Kernel 1: per-code squared norms. One warp per code.
// ---------------------------------------------------------------------------
__global__ void cnorm_kernel(const float* __restrict__ codes) {
    int code = blockIdx.x * 8 + (threadIdx.x >> 5);
    int lane = threadIdx.x & 31;
    float4 v = ((const float4*)(codes + (size_t)code * DIM))[lane];
    float s = v.x * v.x + v.y * v.y + v.z * v.z + v.w * v.w;
    #pragma unroll
    for (int o = 16; o; o >>= 1) s += __shfl_xor_sync(0xFFFFFFFFu, s, o);
    if (lane == 0) g_cnorm[code] = s;
}

// ---------------------------------------------------------------------------
// Kernel 2: fused GEMM + argmin.
// Block: 256 threads, tile 128 rows x (all 4096 codes in 32 chunks of 128).
// smem: xs[k][r] (k-major, 64KB) + cs[k][c] (k-major, 64KB) = 128KB dynamic.
// Each thread: 8x8 micro-tile (rows ty*4+i / 64+ty*4+i, cols tx*4+j / 64+tx*4+j),
// keeps a running (score, idx) argmin per row.
// score = ||c||^2 - 2 x.c  (monotonic in distance; row term constant).
// ---------------------------------------------------------------------------
__global__ __launch_bounds__(256, 1)
void score_kernel(const float* __restrict__ x, const float* __restrict__ codes) {
    extern __shared__ float sm[];
    float* xs = sm;           // [128][128]  xs[k*128 + r]
    float* cs = sm + 16384;   // [128][128]  cs[k*128 + c]

    const int tid = threadIdx.x;
    const int tx  = tid & 15;
    const int ty  = tid >> 4;
    const int rowBase = blockIdx.x << 7;

    // Load + transpose x tile (once). row = tid/2, half-of-K = tid&1.
    {
        int r  = tid >> 1;
        int f0 = (tid & 1) << 4;  // float4 index base (0 or 16)
        const float4* xg = (const float4*)(x + (size_t)(rowBase + r) * DIM);
        #pragma unroll
        for (int it = 0; it < 16; ++it) {
            float4 v = xg[f0 + it];
            int k = (f0 + it) << 2;
            xs[(k + 0) * 128 + r] = v.x;
            xs[(k + 1) * 128 + r] = v.y;
            xs[(k + 2) * 128 + r] = v.z;
            xs[(k + 3) * 128 + r] = v.w;
        }
    }

    float bestS[8];
    int   bestI[8];
    #pragma unroll
    for (int i = 0; i < 8; ++i) { bestS[i] = 3.4e38f; bestI[i] = 0; }

    for (int nt = 0; nt < C_CODES / 128; ++nt) {
        const int colBase = nt << 7;
        __syncthreads();  // protect cs from previous iteration's readers
        {
            int c  = tid >> 1;
            int f0 = (tid & 1) << 4;
            const float4* cg = (const float4*)(codes + (size_t)(colBase + c) * DIM);
            #pragma unroll
            for (int it = 0; it < 16; ++it) {
                float4 v = cg[f0 + it];
                int k = (f0 + it) << 2;
                cs[(k + 0) * 128 + c] = v.x;
                cs[(k + 1) * 128 + c] = v.y;
                cs[(k + 2) * 128 + c] = v.z;
                cs[(k + 3) * 128 + c] = v.w;
            }
        }
        __syncthreads();

        float acc[8][8];
        #pragma unroll
        for (int i = 0; i < 8; ++i)
            #pragma unroll
            for (int j = 0; j < 8; ++j) acc[i][j] = 0.0f;

        #pragma unroll 8
        for (int k = 0; k < 128; ++k) {
            float4 xa = *(const float4*)&xs[k * 128 + (ty << 2)];
            float4 xb = *(const float4*)&xs[k * 128 + 64 + (ty << 2)];
            float4 ca = *(const float4*)&cs[k * 128 + (tx << 2)];
            float4 cb = *(const float4*)&cs[k * 128 + 64 + (tx << 2)];
            float xr[8] = {xa.x, xa.y, xa.z, xa.w, xb.x, xb.y, xb.z, xb.w};
            float cc[8] = {ca.x, ca.y, ca.z, ca.w, cb.x, cb.y, cb.z, cb.w};
            #pragma unroll
            for (int i = 0; i < 8; ++i)
                #pragma unroll
                for (int j = 0; j < 8; ++j)
                    acc[i][j] = fmaf(xr[i], cc[j], acc[i][j]);
        }

        // score + running argmin (columns visited in strictly increasing order
        // within each thread -> strict < keeps the first/lowest index on ties)
        #pragma unroll
        for (int j = 0; j < 8; ++j) {
            int col = colBase + ((j < 4) ? ((tx << 2) + j) : (64 + (tx << 2) + j - 4));
            float cn = g_cnorm[col];
            #pragma unroll
            for (int i = 0; i < 8; ++i) {
                float s = fmaf(-2.0f, acc[i][j], cn);
                if (s < bestS[i]) { bestS[i] = s; bestI[i] = col; }
            }
        }
    }

    // Cross-thread (16 tx lanes per row) argmin reduce via smem (reuse xs area).
    __syncthreads();
    float* rs = sm;                  // [128][16] scores
    int*   ri = (int*)(sm + 2048);   // [128][16] indices
    #pragma unroll
    for (int i = 0; i < 8; ++i) {
        int r = (i < 4) ? ((ty << 2) + i) : (64 + (ty << 2) + i - 4);
        rs[r * 16 + tx] = bestS[i];
        ri[r * 16 + tx] = bestI[i];
    }
    __syncthreads();
    if (tid < 128) {
        int r = tid;
        float bs = rs[r * 16];
        int   bi = ri[r * 16];
        #pragma unroll
        for (int t = 1; t < 16; ++t) {
            float s = rs[r * 16 + t];
            int   c = ri[r * 16 + t];
            if (s < bs || (s == bs && c < bi)) { bs = s; bi = c; }
        }
        g_index[rowBase + r] = bi;
    }
}

// ---------------------------------------------------------------------------
// Kernel 3: gather quantized rows, write indices, accumulate per-block loss
// partial (deterministic: fixed-order per-thread accumulation + tree reduce).
// 512 blocks x 256 threads; block handles 128 contiguous rows (2 rows/iter).
// ---------------------------------------------------------------------------
__global__ void gather_kernel(const float* __restrict__ x,
                              const float* __restrict__ codes,
                              float* __restrict__ outQ,
                              float* __restrict__ outIdx,
                              int wantIdx) {
    const int tid  = threadIdx.x;
    const int r0   = blockIdx.x << 7;
    const int half = tid >> 7;   // 0/1
    const int e    = tid & 127;  // element within row
    float lsum = 0.0f;
    for (int it = 0; it < 64; ++it) {
        int r = r0 + (it << 1) + half;
        int idx = g_index[r];
        float cv = codes[(size_t)idx * DIM + e];
        float xv = x[(size_t)r * DIM + e];
        float d  = xv - cv;
        lsum = fmaf(d, d, lsum);
        outQ[(size_t)r * DIM + e] = cv;
        if (wantIdx && e == 0) outIdx[r] = (float)idx;
    }
    __shared__ float red[256];
    red[tid] = lsum;
    __syncthreads();
    #pragma unroll
    for (int s = 128; s > 0; s >>= 1) {
        if (tid < s) red[tid] += red[tid + s];
        __syncthreads();
    }
    if (tid == 0) g_partial[blockIdx.x] = red[0];
}

// ---------------------------------------------------------------------------
// Kernel 4: final loss reduce. loss = (1 + BETA) * mean(sum (x-q)^2).
// ---------------------------------------------------------------------------
__global__ void loss_kernel(float* __restrict__ outLoss) {
    __shared__ float red[512];
    int tid = threadIdx.x;
    red[tid] = g_partial[tid];
    __syncthreads();
    #pragma unroll
    for (int s = 256; s > 0; s >>= 1) {
        if (tid < s) red[tid] += red[tid + s];
        __syncthreads();
    }
    if (tid == 0) outLoss[0] = 1.25f * red[0] / (float)B_ROWS;
}

// ---------------------------------------------------------------------------
extern "C" void kernel_launch(void* const* d_in, const int* in_sizes, int n_in,
                              void* d_out, int out_size) {
    const float* x     = (const float*)d_in[0];
    const float* codes = (const float*)d_in[1];
    float* out = (float*)d_out;

    cudaFuncSetAttribute(score_kernel,
                         cudaFuncAttributeMaxDynamicSharedMemorySize, 131072);

    cnorm_kernel<<<C_CODES / 8, 256>>>(codes);
    score_kernel<<<B_ROWS / 128, 256, 131072>>>(x, codes);

    long long qElems = (long long)B_ROWS * DIM;
    int wantIdx  = out_size >= (int)(qElems + B_ROWS);
    int wantLoss = out_size >= (int)(qElems + B_ROWS + 1);

    gather_kernel<<<B_ROWS / 128, 256>>>(x, codes, out, out + qElems, wantIdx);
    if (wantLoss) loss_kernel<<<1, 512>>>(out + qElems + B_ROWS);
}

// round 9
// speedup vs baseline: 1.5984x; 1.5984x over previous
#include <cuda_runtime.h>
#include <cuda_bf16.h>
#include <cstdint>
#include <cstddef>

#define B_ROWS  65536
#define C_CODES 4096
#define DIM     128
#define KCAT    384            // 3 bf16 segments of 128
#define MARGIN  0.0625f

// ---------------------------------------------------------------------------
// Scratch (static device globals; no allocations allowed)
// ---------------------------------------------------------------------------
__device__ uint4 g_acat_raw[(size_t)B_ROWS * KCAT * 2 / 16];   // [65536][384] bf16
__device__ uint4 g_bcat_raw[(size_t)C_CODES * KCAT * 2 / 16];  // [4096][384] bf16
__device__ float g_cnorm[C_CODES];
__device__ int   g_index[B_ROWS];
__device__ int   g_index2[B_ROWS];
__device__ int   g_flag[B_ROWS];
__device__ float g_partial[512];

// ---------------------------------------------------------------------------
// PTX helpers (base-target safe: sm_80+ instructions only, NO tcgen05)
// ---------------------------------------------------------------------------
__device__ __forceinline__ uint32_t smem_u32(const void* p) {
    uint32_t a;
    asm("{ .reg .u64 t; cvta.to.shared.u64 t, %1; cvt.u32.u64 %0, t; }" : "=r"(a) : "l"(p));
    return a;
}
#define CP_ASYNC16(dst, src) \
    asm volatile("cp.async.cg.shared.global [%0], [%1], 16;" :: "r"(dst), "l"(src) : "memory")
#define CP_COMMIT()  asm volatile("cp.async.commit_group;" ::: "memory")
#define CP_WAIT1()   asm volatile("cp.async.wait_group 1;" ::: "memory")
#define CP_WAIT0()   asm volatile("cp.async.wait_group 0;" ::: "memory")
#define LDSM_X4(r0, r1, r2, r3, addr) \
    asm volatile("ldmatrix.sync.aligned.m8n8.x4.shared.b16 {%0,%1,%2,%3}, [%4];" \
                 : "=r"(r0), "=r"(r1), "=r"(r2), "=r"(r3) : "r"(addr))
#define MMA16816(d, a0, a1, a2, a3, b0, b1) \
    asm volatile("mma.sync.aligned.m16n8k16.row.col.f32.bf16.bf16.f32 " \
                 "{%0,%1,%2,%3}, {%4,%5,%6,%7}, {%8,%9}, {%0,%1,%2,%3};" \
                 : "+f"((d)[0]), "+f"((d)[1]), "+f"((d)[2]), "+f"((d)[3]) \
                 : "r"(a0), "r"(a1), "r"(a2), "r"(a3), "r"(b0), "r"(b1))

// ---------------------------------------------------------------------------
// Split kernels: fp32 -> bf16 hi/lo, concatenated along K.
// A row = [x_hi | x_hi | x_lo],  B row = [c_hi | c_lo | c_hi]
// ---------------------------------------------------------------------------
__global__ void split_x_kernel(const float* __restrict__ x) {
    int v = blockIdx.x * 256 + threadIdx.x;     // 2,097,152 float4s
    float4 xv = ((const float4*)x)[v];
    int row = v >> 5, c4 = v & 31;
    float f[4] = {xv.x, xv.y, xv.z, xv.w};
    union { __nv_bfloat16 b[4]; uint2 u; } hi, lo;
    #pragma unroll
    for (int i = 0; i < 4; ++i) {
        __nv_bfloat16 h = __float2bfloat16(f[i]);
        hi.b[i] = h;
        lo.b[i] = __float2bfloat16(f[i] - __bfloat162float(h));
    }
    __nv_bfloat16* a = ((__nv_bfloat16*)g_acat_raw) + (size_t)row * KCAT + (c4 << 2);
    *(uint2*)(a)       = hi.u;
    *(uint2*)(a + 128) = hi.u;
    *(uint2*)(a + 256) = lo.u;
}
__global__ void split_c_kernel(const float* __restrict__ codes) {
    int v = blockIdx.x * 256 + threadIdx.x;     // 131,072 float4s
    float4 cv = ((const float4*)codes)[v];
    int row = v >> 5, c4 = v & 31;
    float f[4] = {cv.x, cv.y, cv.z, cv.w};
    union { __nv_bfloat16 b[4]; uint2 u; } hi, lo;
    #pragma unroll
    for (int i = 0; i < 4; ++i) {
        __nv_bfloat16 h = __float2bfloat16(f[i]);
        hi.b[i] = h;
        lo.b[i] = __float2bfloat16(f[i] - __bfloat162float(h));
    }
    __nv_bfloat16* b = ((__nv_bfloat16*)g_bcat_raw) + (size_t)row * KCAT + (c4 << 2);
    *(uint2*)(b)       = hi.u;
    *(uint2*)(b + 128) = lo.u;
    *(uint2*)(b + 256) = hi.u;
}

// ---------------------------------------------------------------------------
// Code squared norms (exact fp32)
// ---------------------------------------------------------------------------
__global__ void cnorm_kernel(const float* __restrict__ codes) {
    int code = blockIdx.x * 8 + (threadIdx.x >> 5);
    int lane = threadIdx.x & 31;
    float4 v = ((const float4*)(codes + (size_t)code * DIM))[lane];
    float s = v.x * v.x + v.y * v.y + v.z * v.z + v.w * v.w;
    #pragma unroll
    for (int o = 16; o; o >>= 1) s += __shfl_xor_sync(0xFFFFFFFFu, s, o);
    if (lane == 0) g_cnorm[code] = s;
}

// ---------------------------------------------------------------------------
// mma.sync score kernel. Grid 512 x 256 threads, 8 warps = 4(M) x 2(N).
// smem: cnorm @0 (16KB), A @16384 (96KB), B0 @114688 (48KB), B1 @163840 (48KB)
// A/B rows are 768B, 16B-unit XOR swizzle: unit' = unit ^ (row&7) within each
// 128B segment -> ldmatrix conflict-free.
// ---------------------------------------------------------------------------
#define SM_CN    0
#define SM_A     16384
#define SM_B0    (SM_A + 98304)     // 114688
#define SM_B1    (SM_B0 + 49152)    // 163840
#define SM_TOTAL (SM_B1 + 49152)    // 212992

__device__ __forceinline__ uint32_t sw_off(int row, int kb) {
    return (uint32_t)(row * 768 + (kb & ~127) + ((((kb >> 4) ^ row) & 7) << 4));
}

__device__ __forceinline__ void issue_b(uint32_t smbase, int nt, int tid) {
    const uint4* src = g_bcat_raw + (size_t)(nt << 6) * 48;
    #pragma unroll
    for (int i = 0; i < 12; ++i) {
        int u   = (i << 8) + tid;        // 0..3071
        int row = u / 48;
        int col = u - row * 48;
        uint32_t dst = smbase + sw_off(row, col << 4);
        CP_ASYNC16(dst, (const void*)(src + row * 48 + col));
    }
}

__global__ __launch_bounds__(256, 1)
void score_mma_kernel() {
    extern __shared__ char sm[];
    const uint32_t smb = smem_u32(sm);
    const int tid  = threadIdx.x;
    const int lane = tid & 31;
    const int w    = tid >> 5;
    const int warpM = w & 3;        // 0..3 -> rows warpM*32
    const int warpN = w >> 2;       // 0..1 -> cols warpN*32

    float* smCn = (float*)(sm + SM_CN);
    #pragma unroll
    for (int i = 0; i < 16; ++i) smCn[(i << 8) + tid] = g_cnorm[(i << 8) + tid];

    // A tile via cp.async (6144 16B units)
    {
        const uint4* asrc = g_acat_raw + (size_t)(blockIdx.x << 7) * 48;
        #pragma unroll
        for (int i = 0; i < 24; ++i) {
            int u   = (i << 8) + tid;
            int row = u / 48;
            int col = u - row * 48;
            uint32_t dst = smb + SM_A + sw_off(row, col << 4);
            CP_ASYNC16(dst, (const void*)(asrc + row * 48 + col));
        }
        CP_COMMIT();
    }
    issue_b(smb + SM_B0, 0, tid);
    CP_COMMIT();

    // per-thread ldmatrix address components (lane-dependent, kstep-independent)
    const int akh = (lane >> 4) << 4;                       // A k-half byte offset
    int arow[2], aterm[2];
    #pragma unroll
    for (int mf = 0; mf < 2; ++mf) {
        arow[mf]  = warpM * 32 + mf * 16 + (lane & 15);
        aterm[mf] = SM_A + arow[mf] * 768;
    }
    const int bkh = ((lane >> 3) & 1) << 4;                 // B k-half byte offset
    int brow[2], bterm[2];
    #pragma unroll
    for (int p = 0; p < 2; ++p) {                           // p covers nf pair {2p, 2p+1}
        brow[p]  = warpN * 32 + p * 16 + ((lane >> 4) << 3) + (lane & 7);
        bterm[p] = brow[p] * 768;
    }

    // per-thread top-3 for 4 row-slots (mf*2 + half)
    float bb[4], bs[4], bt[4];
    int   ib[4], is_[4];
    #pragma unroll
    for (int q = 0; q < 4; ++q) {
        bb[q] = 3.4e38f; bs[q] = 3.4e38f; bt[q] = 3.4e38f;
        ib[q] = 0x7FFFFFFF; is_[q] = 0x7FFFFFFF;
    }

    for (int nt = 0; nt < 64; ++nt) {
        const uint32_t bufbase = smb + ((nt & 1) ? SM_B1 : SM_B0);
        if (nt + 1 < 64) {
            issue_b(smb + ((nt & 1) ? SM_B0 : SM_B1), nt + 1, tid);
            CP_COMMIT();
            CP_WAIT1();
        } else {
            CP_WAIT0();
        }
        __syncthreads();

        float acc[2][4][4];
        #pragma unroll
        for (int mf = 0; mf < 2; ++mf)
            #pragma unroll
            for (int nf = 0; nf < 4; ++nf)
                #pragma unroll
                for (int k = 0; k < 4; ++k) acc[mf][nf][k] = 0.0f;

        #pragma unroll
        for (int s = 0; s < 24; ++s) {
            const int kbA = (s << 5) + akh;
            const int kbB = (s << 5) + bkh;
            uint32_t a0[4], a1[4], r0[4], r1[4];
            {
                uint32_t ad0 = smb + (uint32_t)(aterm[0] + (kbA & ~127)
                               + ((((kbA >> 4) ^ arow[0]) & 7) << 4));
                uint32_t ad1 = smb + (uint32_t)(aterm[1] + (kbA & ~127)
                               + ((((kbA >> 4) ^ arow[1]) & 7) << 4));
                LDSM_X4(a0[0], a0[1], a0[2], a0[3], ad0);
                LDSM_X4(a1[0], a1[1], a1[2], a1[3], ad1);
            }
            {
                uint32_t bd0 = bufbase + (uint32_t)(bterm[0] + (kbB & ~127)
                               + ((((kbB >> 4) ^ brow[0]) & 7) << 4));
                uint32_t bd1 = bufbase + (uint32_t)(bterm[1] + (kbB & ~127)
                               + ((((kbB >> 4) ^ brow[1]) & 7) << 4));
                LDSM_X4(r0[0], r0[1], r0[2], r0[3], bd0);   // nf0 {k0,k8}, nf1 {k0,k8}
                LDSM_X4(r1[0], r1[1], r1[2], r1[3], bd1);   // nf2, nf3
            }
            MMA16816(acc[0][0], a0[0], a0[1], a0[2], a0[3], r0[0], r0[1]);
            MMA16816(acc[0][1], a0[0], a0[1], a0[2], a0[3], r0[2], r0[3]);
            MMA16816(acc[0][2], a0[0], a0[1], a0[2], a0[3], r1[0], r1[1]);
            MMA16816(acc[0][3], a0[0], a0[1], a0[2], a0[3], r1[2], r1[3]);
            MMA16816(acc[1][0], a1[0], a1[1], a1[2], a1[3], r0[0], r0[1]);
            MMA16816(acc[1][1], a1[0], a1[1], a1[2], a1[3], r0[2], r0[3]);
            MMA16816(acc[1][2], a1[0], a1[1], a1[2], a1[3], r1[0], r1[1]);
            MMA16816(acc[1][3], a1[0], a1[1], a1[2], a1[3], r1[2], r1[3]);
        }

        // epilogue: score + online top-3 (cols strictly ascending per thread)
        const int cb = (nt << 6) + warpN * 32 + ((lane & 3) << 1);
        #pragma unroll
        for (int nf = 0; nf < 4; ++nf) {
            #pragma unroll
            for (int j = 0; j < 2; ++j) {
                const int col = cb + nf * 8 + j;
                const float cn = smCn[col];
                #pragma unroll
                for (int mf = 0; mf < 2; ++mf) {
                    #pragma unroll
                    for (int h = 0; h < 2; ++h) {
                        const int q = mf * 2 + h;
                        float s = fmaf(-2.0f, acc[mf][nf][h * 2 + j], cn);
                        if (s < bb[q])      { bt[q] = bs[q]; bs[q] = bb[q]; is_[q] = ib[q]; bb[q] = s; ib[q] = col; }
                        else if (s < bs[q]) { bt[q] = bs[q]; bs[q] = s; is_[q] = col; }
                        else if (s < bt[q]) { bt[q] = s; }
                    }
                }
            }
        }
        __syncthreads();
    }

    // final merge: 8 candidate slots per row (2 N-warps x 4 lane-cols)
    float* exB = (float*)(sm + SM_B0);
    float* exS = exB + 1024;
    float* exT = exS + 1024;
    int*   exI = (int*)(exT + 1024);
    int*   exJ = exI + 1024;
    const int slot = (warpN << 2) + (lane & 3);
    #pragma unroll
    for (int mf = 0; mf < 2; ++mf) {
        #pragma unroll
        for (int h = 0; h < 2; ++h) {
            const int q = mf * 2 + h;
            const int r = warpM * 32 + mf * 16 + h * 8 + (lane >> 2);
            exB[r * 8 + slot] = bb[q]; exS[r * 8 + slot] = bs[q]; exT[r * 8 + slot] = bt[q];
            exI[r * 8 + slot] = ib[q]; exJ[r * 8 + slot] = is_[q];
        }
    }
    __syncthreads();
    if (tid < 128) {
        float b = 3.4e38f, s2 = 3.4e38f, t2 = 3.4e38f;
        int bi = 0x7FFFFFFF, si = 0x7FFFFFFF;
        #pragma unroll
        for (int sl = 0; sl < 8; ++sl) {
            float v0 = exB[tid * 8 + sl], v1 = exS[tid * 8 + sl], v2 = exT[tid * 8 + sl];
            int   i0 = exI[tid * 8 + sl], i1 = exJ[tid * 8 + sl];
            // entry 0
            if (v0 < b || (v0 == b && i0 < bi)) { t2 = s2; s2 = b; si = bi; b = v0; bi = i0; }
            else if (v0 < s2 || (v0 == s2 && i0 < si)) { t2 = s2; s2 = v0; si = i0; }
            else if (v0 < t2) t2 = v0;
            // entry 1
            if (v1 < b || (v1 == b && i1 < bi)) { t2 = s2; s2 = b; si = bi; b = v1; bi = i1; }
            else if (v1 < s2 || (v1 == s2 && i1 < si)) { t2 = s2; s2 = v1; si = i1; }
            else if (v1 < t2) t2 = v1;
            // entry 2 (no index; only matters for the margin check)
            if (v2 < b) { t2 = s2; s2 = b; si = bi; b = v2; bi = 0x7FFFFFFF; }
            else if (v2 < s2) { t2 = s2; s2 = v2; si = 0x7FFFFFFF; }
            else if (v2 < t2) t2 = v2;
        }
        const int row = (blockIdx.x << 7) + tid;
        g_index[row]  = bi;
        g_index2[row] = si;
        int fl = 0;
        if (t2 <= b + MARGIN)      fl = 2;
        else if (s2 <= b + MARGIN) fl = 1;
        g_flag[row] = fl;
    }
}

// ---------------------------------------------------------------------------
// Exact rescan for flagged rows. Grid 512 x 256; block owns 128 rows.
// ---------------------------------------------------------------------------
__global__ void rescan_kernel(const float* __restrict__ x, const float* __restrict__ codes) {
    __shared__ float xs[128];
    __shared__ float rs[256];
    __shared__ int   ri[256];
    const int tid  = threadIdx.x;
    const int base = blockIdx.x << 7;
    for (int rr = 0; rr < 128; ++rr) {
        const int row = base + rr;
        const int fl = g_flag[row];
        if (fl == 0) continue;
        __syncthreads();
        if (tid < 128) xs[tid] = x[(size_t)row * DIM + tid];
        __syncthreads();
        if (fl == 1) {
            const int i0 = g_index[row], i1 = g_index2[row];
            const int c = (tid < 128) ? i0 : i1;
            const int e = tid & 127;
            rs[tid] = xs[e] * codes[(size_t)c * DIM + e];
            __syncthreads();
            #pragma unroll
            for (int st = 64; st; st >>= 1) {
                if ((tid & 127) < st) rs[tid] += rs[tid + st];
                __syncthreads();
            }
            if (tid == 0) {
                float s0 = fmaf(-2.0f, rs[0],   g_cnorm[i0]);
                float s1 = fmaf(-2.0f, rs[128], g_cnorm[i1]);
                g_index[row] = (s1 < s0 || (s1 == s0 && i1 < i0)) ? i1 : i0;
            }
            __syncthreads();
        } else {
            float b = 3.4e38f; int bi = 0;
            for (int c = tid; c < C_CODES; c += 256) {
                const float4* cp = (const float4*)(codes + (size_t)c * DIM);
                const float4* xp = (const float4*)xs;
                float dot = 0.0f;
                #pragma unroll
                for (int k = 0; k < 32; ++k) {
                    float4 cv = cp[k];
                    float4 xv = xp[k];
                    dot += xv.x * cv.x + xv.y * cv.y + xv.z * cv.z + xv.w * cv.w;
                }
                float s = fmaf(-2.0f, dot, g_cnorm[c]);
                if (s < b) { b = s; bi = c; }
            }
            rs[tid] = b; ri[tid] = bi;
            __syncthreads();
            #pragma unroll
            for (int st = 128; st; st >>= 1) {
                if (tid < st) {
                    float s2 = rs[tid + st]; int i2 = ri[tid + st];
                    if (s2 < rs[tid] || (s2 == rs[tid] && i2 < ri[tid])) { rs[tid] = s2; ri[tid] = i2; }
                }
                __syncthreads();
            }
            if (tid == 0) g_index[row] = ri[0];
            __syncthreads();
        }
    }
}

// ---------------------------------------------------------------------------
// Gather + loss
// ---------------------------------------------------------------------------
__global__ void gather_kernel(const float* __restrict__ x,
                              const float* __restrict__ codes,
                              float* __restrict__ outQ,
                              float* __restrict__ outIdx,
                              int wantIdx) {
    const int tid  = threadIdx.x;
    const int r0   = blockIdx.x << 7;
    const int half = tid >> 7;
    const int e    = tid & 127;
    float lsum = 0.0f;
    for (int it = 0; it < 64; ++it) {
        int r = r0 + (it << 1) + half;
        int idx = g_index[r];
        float cv = codes[(size_t)idx * DIM + e];
        float xv = x[(size_t)r * DIM + e];
        float d  = xv - cv;
        lsum = fmaf(d, d, lsum);
        outQ[(size_t)r * DIM + e] = cv;
        if (wantIdx && e == 0) outIdx[r] = (float)idx;
    }
    __shared__ float red[256];
    red[tid] = lsum;
    __syncthreads();
    #pragma unroll
    for (int s = 128; s > 0; s >>= 1) {
        if (tid < s) red[tid] += red[tid + s];
        __syncthreads();
    }
    if (tid == 0) g_partial[blockIdx.x] = red[0];
}

__global__ void loss_kernel(float* __restrict__ outLoss) {
    __shared__ float red[512];
    int tid = threadIdx.x;
    red[tid] = g_partial[tid];
    __syncthreads();
    #pragma unroll
    for (int s = 256; s > 0; s >>= 1) {
        if (tid < s) red[tid] += red[tid + s];
        __syncthreads();
    }
    if (tid == 0) outLoss[0] = 1.25f * red[0] / (float)B_ROWS;
}

// ---------------------------------------------------------------------------
extern "C" void kernel_launch(void* const* d_in, const int* in_sizes, int n_in,
                              void* d_out, int out_size) {
    const float* x     = (const float*)d_in[0];
    const float* codes = (const float*)d_in[1];
    float* out = (float*)d_out;

    cudaFuncSetAttribute(score_mma_kernel,
                         cudaFuncAttributeMaxDynamicSharedMemorySize, SM_TOTAL);

    split_x_kernel<<<8192, 256>>>(x);
    split_c_kernel<<<512, 256>>>(codes);
    cnorm_kernel<<<C_CODES / 8, 256>>>(codes);
    score_mma_kernel<<<B_ROWS / 128, 256, SM_TOTAL>>>();
    rescan_kernel<<<512, 256>>>(x, codes);

    long long qElems = (long long)B_ROWS * DIM;
    int wantIdx  = out_size >= (int)(qElems + B_ROWS);
    int wantLoss = out_size >= (int)(qElems + B_ROWS + 1);

    gather_kernel<<<B_ROWS / 128, 256>>>(x, codes, out, out + qElems, wantIdx);
    if (wantLoss) loss_kernel<<<1, 512>>>(out + qElems + B_ROWS);
}

// round 11
// speedup vs baseline: 1.6921x; 1.0586x over previous
#include <cuda_runtime.h>
#include <cuda_bf16.h>
#include <cstdint>
#include <cstddef>

#define B_ROWS  65536
#define C_CODES 4096
#define DIM     128
#define MARGIN  0.0625f

// ---------------------------------------------------------------------------
// Scratch: K=256 bf16 rows: [hi(128) | lo(128)]  (512 B = 32 uint4 per row)
// ---------------------------------------------------------------------------
__device__ uint4 g_acat_raw[(size_t)B_ROWS * 32];   // [65536][256] bf16
__device__ uint4 g_bcat_raw[(size_t)C_CODES * 32];  // [4096][256] bf16
__device__ float g_cnorm[C_CODES];
__device__ int   g_index[B_ROWS];
__device__ int   g_index2[B_ROWS];
__device__ int   g_flag[B_ROWS];
__device__ float g_partial[512];

// ---------------------------------------------------------------------------
// PTX helpers (base-target safe: sm_80+ only)
// ---------------------------------------------------------------------------
__device__ __forceinline__ uint32_t smem_u32(const void* p) {
    uint32_t a;
    asm("{ .reg .u64 t; cvta.to.shared.u64 t, %1; cvt.u32.u64 %0, t; }" : "=r"(a) : "l"(p));
    return a;
}
#define CP_ASYNC16(dst, src) \
    asm volatile("cp.async.cg.shared.global [%0], [%1], 16;" :: "r"(dst), "l"(src) : "memory")
#define CP_COMMIT()  asm volatile("cp.async.commit_group;" ::: "memory")
#define CP_WAIT1()   asm volatile("cp.async.wait_group 1;" ::: "memory")
#define CP_WAIT0()   asm volatile("cp.async.wait_group 0;" ::: "memory")
#define LDSM_X4(r0, r1, r2, r3, addr) \
    asm volatile("ldmatrix.sync.aligned.m8n8.x4.shared.b16 {%0,%1,%2,%3}, [%4];" \
                 : "=r"(r0), "=r"(r1), "=r"(r2), "=r"(r3) : "r"(addr))
#define MMA16816(d, a0, a1, a2, a3, b0, b1) \
    asm volatile("mma.sync.aligned.m16n8k16.row.col.f32.bf16.bf16.f32 " \
                 "{%0,%1,%2,%3}, {%4,%5,%6,%7}, {%8,%9}, {%0,%1,%2,%3};" \
                 : "+f"((d)[0]), "+f"((d)[1]), "+f"((d)[2]), "+f"((d)[3]) \
                 : "r"(a0), "r"(a1), "r"(a2), "r"(a3), "r"(b0), "r"(b1))

// ---------------------------------------------------------------------------
// Split kernels: fp32 -> bf16 hi/lo, row = [hi | lo] (K=256)
// ---------------------------------------------------------------------------
__global__ void split_x_kernel(const float* __restrict__ x) {
    int v = blockIdx.x * 256 + threadIdx.x;     // 2,097,152 float4s
    float4 xv = ((const float4*)x)[v];
    int row = v >> 5, c4 = v & 31;
    float f[4] = {xv.x, xv.y, xv.z, xv.w};
    union { __nv_bfloat16 b[4]; uint2 u; } hi, lo;
    #pragma unroll
    for (int i = 0; i < 4; ++i) {
        __nv_bfloat16 h = __float2bfloat16(f[i]);
        hi.b[i] = h;
        lo.b[i] = __float2bfloat16(f[i] - __bfloat162float(h));
    }
    __nv_bfloat16* a = ((__nv_bfloat16*)g_acat_raw) + (size_t)row * 256 + (c4 << 2);
    *(uint2*)(a)       = hi.u;
    *(uint2*)(a + 128) = lo.u;
}
__global__ void split_c_kernel(const float* __restrict__ codes) {
    int v = blockIdx.x * 256 + threadIdx.x;     // 131,072 float4s
    float4 cv = ((const float4*)codes)[v];
    int row = v >> 5, c4 = v & 31;
    float f[4] = {cv.x, cv.y, cv.z, cv.w};
    union { __nv_bfloat16 b[4]; uint2 u; } hi, lo;
    #pragma unroll
    for (int i = 0; i < 4; ++i) {
        __nv_bfloat16 h = __float2bfloat16(f[i]);
        hi.b[i] = h;
        lo.b[i] = __float2bfloat16(f[i] - __bfloat162float(h));
    }
    __nv_bfloat16* b = ((__nv_bfloat16*)g_bcat_raw) + (size_t)row * 256 + (c4 << 2);
    *(uint2*)(b)       = hi.u;
    *(uint2*)(b + 128) = lo.u;
}

// ---------------------------------------------------------------------------
// Code squared norms (exact fp32)
// ---------------------------------------------------------------------------
__global__ void cnorm_kernel(const float* __restrict__ codes) {
    int code = blockIdx.x * 8 + (threadIdx.x >> 5);
    int lane = threadIdx.x & 31;
    float4 v = ((const float4*)(codes + (size_t)code * DIM))[lane];
    float s = v.x * v.x + v.y * v.y + v.z * v.z + v.w * v.w;
    #pragma unroll
    for (int o = 16; o; o >>= 1) s += __shfl_xor_sync(0xFFFFFFFFu, s, o);
    if (lane == 0) g_cnorm[code] = s;
}

// ---------------------------------------------------------------------------
// mma.sync score kernel. Grid 512 x 256 threads, 8 warps = 4(M) x 2(N).
// CTA tile: 128 rows x 128 codes per iteration (32 iterations).
// Warp tile: 32 rows x 64 codes. Products: hi*hi + hi*lo + lo*hi with
// fragment reuse (12 LDSM : 48 MMA per k16-step).
// smem rows are 512B; 16B-unit XOR swizzle within each 128B segment.
// ---------------------------------------------------------------------------
#define SM_CN    0
#define SM_A     16384
#define SM_B0    (SM_A + 65536)     // 81920
#define SM_B1    (SM_B0 + 65536)    // 147456
#define SM_TOTAL (SM_B1 + 65536)    // 212992

__device__ __forceinline__ void issue_b(uint32_t smbase, int nt, int tid) {
    const uint4* src = g_bcat_raw + (size_t)(nt << 7) * 32;
    #pragma unroll
    for (int i = 0; i < 16; ++i) {
        int u    = (i << 8) + tid;          // 0..4095
        int row  = u >> 5;
        int unit = u & 31;
        uint32_t dst = smbase + (uint32_t)((row << 9) + ((unit & ~7) << 4)
                         + ((((unit ^ row) & 7)) << 4));
        CP_ASYNC16(dst, (const void*)(src + (row << 5) + unit));
    }
}

__global__ __launch_bounds__(256, 1)
void score_mma_kernel() {
    extern __shared__ char sm[];
    const uint32_t smb = smem_u32(sm);
    const int tid  = threadIdx.x;
    const int lane = tid & 31;
    const int w    = tid >> 5;
    const int warpM = w & 3;        // rows warpM*32
    const int warpN = w >> 2;       // cols warpN*64

    float* smCn = (float*)(sm + SM_CN);
    #pragma unroll
    for (int i = 0; i < 16; ++i) smCn[(i << 8) + tid] = g_cnorm[(i << 8) + tid];

    // A tile via cp.async (4096 16B units)
    {
        const uint4* asrc = g_acat_raw + (size_t)(blockIdx.x << 7) * 32;
        #pragma unroll
        for (int i = 0; i < 16; ++i) {
            int u    = (i << 8) + tid;
            int row  = u >> 5;
            int unit = u & 31;
            uint32_t dst = smb + SM_A + (uint32_t)((row << 9) + ((unit & ~7) << 4)
                             + ((((unit ^ row) & 7)) << 4));
            CP_ASYNC16(dst, (const void*)(asrc + (row << 5) + unit));
        }
        CP_COMMIT();
    }
    issue_b(smb + SM_B0, 0, tid);
    CP_COMMIT();

    // ldmatrix lane address components
    const int akh = (lane >> 4) << 4;                 // A k-half byte offset
    int arow[2], aterm[2];
    #pragma unroll
    for (int mf = 0; mf < 2; ++mf) {
        arow[mf]  = warpM * 32 + mf * 16 + (lane & 15);
        aterm[mf] = SM_A + (arow[mf] << 9);
    }
    const int bkh = ((lane >> 3) & 1) << 4;           // B k-half byte offset
    int brow[4], bterm[4];
    #pragma unroll
    for (int p = 0; p < 4; ++p) {                     // p covers nf pair {2p, 2p+1}
        brow[p]  = warpN * 64 + p * 16 + ((lane >> 4) << 3) + (lane & 7);
        bterm[p] = brow[p] << 9;
    }

    // per-thread top-3 for 4 row-slots (mf*2 + half)
    float bb[4], bs[4], bt[4];
    int   ib[4], is_[4];
    #pragma unroll
    for (int q = 0; q < 4; ++q) {
        bb[q] = 3.4e38f; bs[q] = 3.4e38f; bt[q] = 3.4e38f;
        ib[q] = 0x7FFFFFFF; is_[q] = 0x7FFFFFFF;
    }

    for (int nt = 0; nt < 32; ++nt) {
        const uint32_t bufbase = smb + ((nt & 1) ? SM_B1 : SM_B0);
        if (nt + 1 < 32) {
            issue_b(smb + ((nt & 1) ? SM_B0 : SM_B1), nt + 1, tid);
            CP_COMMIT();
            CP_WAIT1();
        } else {
            CP_WAIT0();
        }
        __syncthreads();

        float acc[2][8][4];
        #pragma unroll
        for (int mf = 0; mf < 2; ++mf)
            #pragma unroll
            for (int nf = 0; nf < 8; ++nf)
                #pragma unroll
                for (int k = 0; k < 4; ++k) acc[mf][nf][k] = 0.0f;

        #pragma unroll
        for (int s = 0; s < 8; ++s) {
            const int kbA0 = (s << 5) + akh;          // A hi segment
            const int kbA1 = 256 + kbA0;              // A lo segment
            const int kbB0 = (s << 5) + bkh;          // B hi segment
            const int kbB1 = 256 + kbB0;              // B lo segment

            uint32_t aH[2][4], aL[2][4];
            #pragma unroll
            for (int mf = 0; mf < 2; ++mf) {
                uint32_t adH = smb + (uint32_t)(aterm[mf] + (kbA0 & ~127)
                               + ((((kbA0 >> 4) ^ arow[mf]) & 7) << 4));
                uint32_t adL = smb + (uint32_t)(aterm[mf] + (kbA1 & ~127)
                               + ((((kbA1 >> 4) ^ arow[mf]) & 7) << 4));
                LDSM_X4(aH[mf][0], aH[mf][1], aH[mf][2], aH[mf][3], adH);
                LDSM_X4(aL[mf][0], aL[mf][1], aL[mf][2], aL[mf][3], adL);
            }

            // B hi segment: hi*hi and lo*hi
            #pragma unroll
            for (int p = 0; p < 4; ++p) {
                uint32_t bH[4];
                uint32_t bd = bufbase + (uint32_t)(bterm[p] + (kbB0 & ~127)
                               + ((((kbB0 >> 4) ^ brow[p]) & 7) << 4));
                LDSM_X4(bH[0], bH[1], bH[2], bH[3], bd);
                #pragma unroll
                for (int mf = 0; mf < 2; ++mf) {
                    MMA16816(acc[mf][2 * p],     aH[mf][0], aH[mf][1], aH[mf][2], aH[mf][3], bH[0], bH[1]);
                    MMA16816(acc[mf][2 * p + 1], aH[mf][0], aH[mf][1], aH[mf][2], aH[mf][3], bH[2], bH[3]);
                    MMA16816(acc[mf][2 * p],     aL[mf][0], aL[mf][1], aL[mf][2], aL[mf][3], bH[0], bH[1]);
                    MMA16816(acc[mf][2 * p + 1], aL[mf][0], aL[mf][1], aL[mf][2], aL[mf][3], bH[2], bH[3]);
                }
            }
            // B lo segment: hi*lo
            #pragma unroll
            for (int p = 0; p < 4; ++p) {
                uint32_t bL[4];
                uint32_t bd = bufbase + (uint32_t)(bterm[p] + (kbB1 & ~127)
                               + ((((kbB1 >> 4) ^ brow[p]) & 7) << 4));
                LDSM_X4(bL[0], bL[1], bL[2], bL[3], bd);
                #pragma unroll
                for (int mf = 0; mf < 2; ++mf) {
                    MMA16816(acc[mf][2 * p],     aH[mf][0], aH[mf][1], aH[mf][2], aH[mf][3], bL[0], bL[1]);
                    MMA16816(acc[mf][2 * p + 1], aH[mf][0], aH[mf][1], aH[mf][2], aH[mf][3], bL[2], bL[3]);
                }
            }
        }

        // epilogue: score + online top-3 (cols strictly ascending per thread)
        const int cb = (nt << 7) + warpN * 64 + ((lane & 3) << 1);
        #pragma unroll
        for (int nf = 0; nf < 8; ++nf) {
            #pragma unroll
            for (int j = 0; j < 2; ++j) {
                const int col = cb + nf * 8 + j;
                const float cn = smCn[col];
                #pragma unroll
                for (int mf = 0; mf < 2; ++mf) {
                    #pragma unroll
                    for (int h = 0; h < 2; ++h) {
                        const int q = mf * 2 + h;
                        float s = fmaf(-2.0f, acc[mf][nf][h * 2 + j], cn);
                        if (s < bb[q])      { bt[q] = bs[q]; bs[q] = bb[q]; is_[q] = ib[q]; bb[q] = s; ib[q] = col; }
                        else if (s < bs[q]) { bt[q] = bs[q]; bs[q] = s; is_[q] = col; }
                        else if (s < bt[q]) { bt[q] = s; }
                    }
                }
            }
        }
        __syncthreads();
    }

    // final merge: 8 candidate slots per row (2 N-warps x 4 lane-cols)
    float* exB = (float*)(sm + SM_B0);
    float* exS = exB + 1024;
    float* exT = exS + 1024;
    int*   exI = (int*)(exT + 1024);
    int*   exJ = exI + 1024;
    const int slot = (warpN << 2) + (lane & 3);
    #pragma unroll
    for (int mf = 0; mf < 2; ++mf) {
        #pragma unroll
        for (int h = 0; h < 2; ++h) {
            const int q = mf * 2 + h;
            const int r = warpM * 32 + mf * 16 + h * 8 + (lane >> 2);
            exB[r * 8 + slot] = bb[q]; exS[r * 8 + slot] = bs[q]; exT[r * 8 + slot] = bt[q];
            exI[r * 8 + slot] = ib[q]; exJ[r * 8 + slot] = is_[q];
        }
    }
    __syncthreads();
    if (tid < 128) {
        float b = 3.4e38f, s2 = 3.4e38f, t2 = 3.4e38f;
        int bi = 0x7FFFFFFF, si = 0x7FFFFFFF;
        #pragma unroll
        for (int sl = 0; sl < 8; ++sl) {
            float v0 = exB[tid * 8 + sl], v1 = exS[tid * 8 + sl], v2 = exT[tid * 8 + sl];
            int   i0 = exI[tid * 8 + sl], i1 = exJ[tid * 8 + sl];
            if (v0 < b || (v0 == b && i0 < bi)) { t2 = s2; s2 = b; si = bi; b = v0; bi = i0; }
            else if (v0 < s2 || (v0 == s2 && i0 < si)) { t2 = s2; s2 = v0; si = i0; }
            else if (v0 < t2) t2 = v0;
            if (v1 < b || (v1 == b && i1 < bi)) { t2 = s2; s2 = b; si = bi; b = v1; bi = i1; }
            else if (v1 < s2 || (v1 == s2 && i1 < si)) { t2 = s2; s2 = v1; si = i1; }
            else if (v1 < t2) t2 = v1;
            if (v2 < b) { t2 = s2; s2 = b; si = bi; b = v2; bi = 0x7FFFFFFF; }
            else if (v2 < s2) { t2 = s2; s2 = v2; si = 0x7FFFFFFF; }
            else if (v2 < t2) t2 = v2;
        }
        const int row = (blockIdx.x << 7) + tid;
        g_index[row]  = bi;
        g_index2[row] = si;
        int fl = 0;
        if (t2 <= b + MARGIN)      fl = 2;
        else if (s2 <= b + MARGIN) fl = 1;
        g_flag[row] = fl;
    }
}

// ---------------------------------------------------------------------------
// Exact rescan for flagged rows. Grid 512 x 256; block owns 128 rows.
// ---------------------------------------------------------------------------
__global__ void rescan_kernel(const float* __restrict__ x, const float* __restrict__ codes) {
    __shared__ float xs[128];
    __shared__ float rs[256];
    __shared__ int   ri[256];
    const int tid  = threadIdx.x;
    const int base = blockIdx.x << 7;
    for (int rr = 0; rr < 128; ++rr) {
        const int row = base + rr;
        const int fl = g_flag[row];
        if (fl == 0) continue;
        __syncthreads();
        if (tid < 128) xs[tid] = x[(size_t)row * DIM + tid];
        __syncthreads();
        if (fl == 1) {
            const int i0 = g_index[row], i1 = g_index2[row];
            const int c = (tid < 128) ? i0 : i1;
            const int e = tid & 127;
            rs[tid] = xs[e] * codes[(size_t)c * DIM + e];
            __syncthreads();
            #pragma unroll
            for (int st = 64; st; st >>= 1) {
                if ((tid & 127) < st) rs[tid] += rs[tid + st];
                __syncthreads();
            }
            if (tid == 0) {
                float s0 = fmaf(-2.0f, rs[0],   g_cnorm[i0]);
                float s1 = fmaf(-2.0f, rs[128], g_cnorm[i1]);
                g_index[row] = (s1 < s0 || (s1 == s0 && i1 < i0)) ? i1 : i0;
            }
            __syncthreads();
        } else {
            float b = 3.4e38f; int bi = 0;
            for (int c = tid; c < C_CODES; c += 256) {
                const float4* cp = (const float4*)(codes + (size_t)c * DIM);
                const float4* xp = (const float4*)xs;
                float dot = 0.0f;
                #pragma unroll
                for (int k = 0; k < 32; ++k) {
                    float4 cv = cp[k];
                    float4 xv = xp[k];
                    dot += xv.x * cv.x + xv.y * cv.y + xv.z * cv.z + xv.w * cv.w;
                }
                float s = fmaf(-2.0f, dot, g_cnorm[c]);
                if (s < b) { b = s; bi = c; }
            }
            rs[tid] = b; ri[tid] = bi;
            __syncthreads();
            #pragma unroll
            for (int st = 128; st; st >>= 1) {
                if (tid < st) {
                    float s2 = rs[tid + st]; int i2 = ri[tid + st];
                    if (s2 < rs[tid] || (s2 == rs[tid] && i2 < ri[tid])) { rs[tid] = s2; ri[tid] = i2; }
                }
                __syncthreads();
            }
            if (tid == 0) g_index[row] = ri[0];
            __syncthreads();
        }
    }
}

// ---------------------------------------------------------------------------
// Gather + loss
// ---------------------------------------------------------------------------
__global__ void gather_kernel(const float* __restrict__ x,
                              const float* __restrict__ codes,
                              float* __restrict__ outQ,
                              float* __restrict__ outIdx,
                              int wantIdx) {
    const int tid  = threadIdx.x;
    const int r0   = blockIdx.x << 7;
    const int half = tid >> 7;
    const int e    = tid & 127;
    float lsum = 0.0f;
    for (int it = 0; it < 64; ++it) {
        int r = r0 + (it << 1) + half;
        int idx = g_index[r];
        float cv = codes[(size_t)idx * DIM + e];
        float xv = x[(size_t)r * DIM + e];
        float d  = xv - cv;
        lsum = fmaf(d, d, lsum);
        outQ[(size_t)r * DIM + e] = cv;
        if (wantIdx && e == 0) outIdx[r] = (float)idx;
    }
    __shared__ float red[256];
    red[tid] = lsum;
    __syncthreads();
    #pragma unroll
    for (int s = 128; s > 0; s >>= 1) {
        if (tid < s) red[tid] += red[tid + s];
        __syncthreads();
    }
    if (tid == 0) g_partial[blockIdx.x] = red[0];
}

__global__ void loss_kernel(float* __restrict__ outLoss) {
    __shared__ float red[512];
    int tid = threadIdx.x;
    red[tid] = g_partial[tid];
    __syncthreads();
    #pragma unroll
    for (int s = 256; s > 0; s >>= 1) {
        if (tid < s) red[tid] += red[tid + s];
        __syncthreads();
    }
    if (tid == 0) outLoss[0] = 1.25f * red[0] / (float)B_ROWS;
}

// ---------------------------------------------------------------------------
extern "C" void kernel_launch(void* const* d_in, const int* in_sizes, int n_in,
                              void* d_out, int out_size) {
    const float* x     = (const float*)d_in[0];
    const float* codes = (const float*)d_in[1];
    float* out = (float*)d_out;

    cudaFuncSetAttribute(score_mma_kernel,
                         cudaFuncAttributeMaxDynamicSharedMemorySize, SM_TOTAL);

    split_x_kernel<<<8192, 256>>>(x);
    split_c_kernel<<<512, 256>>>(codes);
    cnorm_kernel<<<C_CODES / 8, 256>>>(codes);
    score_mma_kernel<<<B_ROWS / 128, 256, SM_TOTAL>>>();
    rescan_kernel<<<512, 256>>>(x, codes);

    long long qElems = (long long)B_ROWS * DIM;
    int wantIdx  = out_size >= (int)(qElems + B_ROWS);
    int wantLoss = out_size >= (int)(qElems + B_ROWS + 1);

    gather_kernel<<<B_ROWS / 128, 256>>>(x, codes, out, out + qElems, wantIdx);
    if (wantLoss) loss_kernel<<<1, 512>>>(out + qElems + B_ROWS);
}

// round 14
// speedup vs baseline: 1.8833x; 1.1130x over previous
#include <cuda_runtime.h>
#include <cuda_bf16.h>
#include <cstdint>
#include <cstddef>

#define B_ROWS  65536
#define C_CODES 4096
#define DIM     128
#define MARGIN  0.0625f

// ---------------------------------------------------------------------------
// Scratch: K=256 bf16 rows: [hi(128) | lo(128)]  (512 B = 32 uint4 per row)
// ---------------------------------------------------------------------------
__device__ uint4 g_acat_raw[(size_t)B_ROWS * 32];   // [65536][256] bf16
__device__ uint4 g_bcat_raw[(size_t)C_CODES * 32];  // [4096][256] bf16
__device__ float g_cnorm[C_CODES];
__device__ int   g_index[B_ROWS];
__device__ int   g_index2[B_ROWS];
__device__ int   g_flag[B_ROWS];
__device__ float g_partial[512];

// ---------------------------------------------------------------------------
// PTX helpers (base-target safe: sm_80+ only)
// ---------------------------------------------------------------------------
__device__ __forceinline__ uint32_t smem_u32(const void* p) {
    uint32_t a;
    asm("{ .reg .u64 t; cvta.to.shared.u64 t, %1; cvt.u32.u64 %0, t; }" : "=r"(a) : "l"(p));
    return a;
}
#define CP_ASYNC16(dst, src) \
    asm volatile("cp.async.cg.shared.global [%0], [%1], 16;" :: "r"(dst), "l"(src) : "memory")
#define CP_COMMIT()  asm volatile("cp.async.commit_group;" ::: "memory")
#define CP_WAIT1()   asm volatile("cp.async.wait_group 1;" ::: "memory")
#define CP_WAIT0()   asm volatile("cp.async.wait_group 0;" ::: "memory")
#define LDSM_X4(r0, r1, r2, r3, addr) \
    asm volatile("ldmatrix.sync.aligned.m8n8.x4.shared.b16 {%0,%1,%2,%3}, [%4];" \
                 : "=r"(r0), "=r"(r1), "=r"(r2), "=r"(r3) : "r"(addr))
#define MMA16816(d, a0, a1, a2, a3, b0, b1) \
    asm volatile("mma.sync.aligned.m16n8k16.row.col.f32.bf16.bf16.f32 " \
                 "{%0,%1,%2,%3}, {%4,%5,%6,%7}, {%8,%9}, {%0,%1,%2,%3};" \
                 : "+f"((d)[0]), "+f"((d)[1]), "+f"((d)[2]), "+f"((d)[3]) \
                 : "r"(a0), "r"(a1), "r"(a2), "r"(a3), "r"(b0), "r"(b1))

// ---------------------------------------------------------------------------
// Split kernels: fp32 -> bf16 hi/lo, row = [hi | lo] (K=256)
// ---------------------------------------------------------------------------
__global__ void split_x_kernel(const float* __restrict__ x) {
    int v = blockIdx.x * 256 + threadIdx.x;     // 2,097,152 float4s
    float4 xv = ((const float4*)x)[v];
    int row = v >> 5, c4 = v & 31;
    float f[4] = {xv.x, xv.y, xv.z, xv.w};
    union { __nv_bfloat16 b[4]; uint2 u; } hi, lo;
    #pragma unroll
    for (int i = 0; i < 4; ++i) {
        __nv_bfloat16 h = __float2bfloat16(f[i]);
        hi.b[i] = h;
        lo.b[i] = __float2bfloat16(f[i] - __bfloat162float(h));
    }
    __nv_bfloat16* a = ((__nv_bfloat16*)g_acat_raw) + (size_t)row * 256 + (c4 << 2);
    *(uint2*)(a)       = hi.u;
    *(uint2*)(a + 128) = lo.u;
}
__global__ void split_c_kernel(const float* __restrict__ codes) {
    int v = blockIdx.x * 256 + threadIdx.x;     // 131,072 float4s
    float4 cv = ((const float4*)codes)[v];
    int row = v >> 5, c4 = v & 31;
    float f[4] = {cv.x, cv.y, cv.z, cv.w};
    union { __nv_bfloat16 b[4]; uint2 u; } hi, lo;
    #pragma unroll
    for (int i = 0; i < 4; ++i) {
        __nv_bfloat16 h = __float2bfloat16(f[i]);
        hi.b[i] = h;
        lo.b[i] = __float2bfloat16(f[i] - __bfloat162float(h));
    }
    __nv_bfloat16* b = ((__nv_bfloat16*)g_bcat_raw) + (size_t)row * 256 + (c4 << 2);
    *(uint2*)(b)       = hi.u;
    *(uint2*)(b + 128) = lo.u;
}

// ---------------------------------------------------------------------------
// Code squared norms (exact fp32)
// ---------------------------------------------------------------------------
__global__ void cnorm_kernel(const float* __restrict__ codes) {
    int code = blockIdx.x * 8 + (threadIdx.x >> 5);
    int lane = threadIdx.x & 31;
    float4 v = ((const float4*)(codes + (size_t)code * DIM))[lane];
    float s = v.x * v.x + v.y * v.y + v.z * v.z + v.w * v.w;
    #pragma unroll
    for (int o = 16; o; o >>= 1) s += __shfl_xor_sync(0xFFFFFFFFu, s, o);
    if (lane == 0) g_cnorm[code] = s;
}

// ---------------------------------------------------------------------------
// mma.sync score kernel. Grid 512 x 512 threads, 16 warps = 4(M) x 4(N).
// CTA tile: 128 rows x 128 codes per iteration (32 iterations).
// Warp tile: 32 rows x 32 codes. Products: hi*hi + hi*lo + lo*hi with
// fragment reuse; 3-pass MMA ordering keeps same-accumulator writes >= 8
// MMAs apart. 16 warps/SM (4 per SMSP) for latency hiding.
// smem rows are 512B; 16B-unit XOR swizzle within each 128B segment.
// ---------------------------------------------------------------------------
#define SM_CN    0
#define SM_A     16384
#define SM_B0    (SM_A + 65536)     // 81920
#define SM_B1    (SM_B0 + 65536)    // 147456
#define SM_TOTAL (SM_B1 + 65536)    // 212992

__device__ __forceinline__ void issue_b(uint32_t smbase, int nt, int tid) {
    const uint4* src = g_bcat_raw + (size_t)(nt << 7) * 32;
    #pragma unroll
    for (int i = 0; i < 8; ++i) {
        int u    = (i << 9) + tid;          // 0..4095
        int row  = u >> 5;
        int unit = u & 31;
        uint32_t dst = smbase + (uint32_t)((row << 9) + ((unit & ~7) << 4)
                         + ((((unit ^ row) & 7)) << 4));
        CP_ASYNC16(dst, (const void*)(src + (row << 5) + unit));
    }
}

__global__ __launch_bounds__(512, 1)
void score_mma_kernel() {
    extern __shared__ char sm[];
    const uint32_t smb = smem_u32(sm);
    const int tid  = threadIdx.x;
    const int lane = tid & 31;
    const int w    = tid >> 5;      // 0..15
    const int warpM = w & 3;        // rows warpM*32
    const int warpN = w >> 2;       // cols warpN*32

    float* smCn = (float*)(sm + SM_CN);
    #pragma unroll
    for (int i = 0; i < 8; ++i) smCn[(i << 9) + tid] = g_cnorm[(i << 9) + tid];

    // A tile via cp.async (4096 16B units, 8 per thread)
    {
        const uint4* asrc = g_acat_raw + (size_t)(blockIdx.x << 7) * 32;
        #pragma unroll
        for (int i = 0; i < 8; ++i) {
            int u    = (i << 9) + tid;
            int row  = u >> 5;
            int unit = u & 31;
            uint32_t dst = smb + SM_A + (uint32_t)((row << 9) + ((unit & ~7) << 4)
                             + ((((unit ^ row) & 7)) << 4));
            CP_ASYNC16(dst, (const void*)(asrc + (row << 5) + unit));
        }
        CP_COMMIT();
    }
    issue_b(smb + SM_B0, 0, tid);
    CP_COMMIT();

    // ldmatrix lane address components
    const int akh = (lane >> 4) << 4;                 // A k-half byte offset
    int arow[2], aterm[2];
    #pragma unroll
    for (int mf = 0; mf < 2; ++mf) {
        arow[mf]  = warpM * 32 + mf * 16 + (lane & 15);
        aterm[mf] = SM_A + (arow[mf] << 9);
    }
    const int bkh = ((lane >> 3) & 1) << 4;           // B k-half byte offset
    int brow[2], bterm[2];
    #pragma unroll
    for (int p = 0; p < 2; ++p) {                     // p covers nf pair {2p, 2p+1}
        brow[p]  = warpN * 32 + p * 16 + ((lane >> 4) << 3) + (lane & 7);
        bterm[p] = brow[p] << 9;
    }

    // per-thread top-3 for 4 row-slots (mf*2 + half)
    float bb[4], bs[4], bt[4];
    int   ib[4], is_[4];
    #pragma unroll
    for (int q = 0; q < 4; ++q) {
        bb[q] = 3.4e38f; bs[q] = 3.4e38f; bt[q] = 3.4e38f;
        ib[q] = 0x7FFFFFFF; is_[q] = 0x7FFFFFFF;
    }

    for (int nt = 0; nt < 32; ++nt) {
        const uint32_t bufbase = smb + ((nt & 1) ? SM_B1 : SM_B0);
        if (nt + 1 < 32) {
            issue_b(smb + ((nt & 1) ? SM_B0 : SM_B1), nt + 1, tid);
            CP_COMMIT();
            CP_WAIT1();
        } else {
            CP_WAIT0();
        }
        __syncthreads();

        float acc[2][4][4];
        #pragma unroll
        for (int mf = 0; mf < 2; ++mf)
            #pragma unroll
            for (int nf = 0; nf < 4; ++nf)
                #pragma unroll
                for (int k = 0; k < 4; ++k) acc[mf][nf][k] = 0.0f;

        #pragma unroll
        for (int s = 0; s < 8; ++s) {
            const int kbA0 = (s << 5) + akh;          // A hi segment
            const int kbA1 = 256 + kbA0;              // A lo segment
            const int kbB0 = (s << 5) + bkh;          // B hi segment
            const int kbB1 = 256 + kbB0;              // B lo segment

            // all hi-side LDSMs up front: latency covered by pass-1 MMAs
            uint32_t aH[2][4], aL[2][4], bH[2][4];
            #pragma unroll
            for (int mf = 0; mf < 2; ++mf) {
                uint32_t adH = smb + (uint32_t)(aterm[mf] + (kbA0 & ~127)
                               + ((((kbA0 >> 4) ^ arow[mf]) & 7) << 4));
                uint32_t adL = smb + (uint32_t)(aterm[mf] + (kbA1 & ~127)
                               + ((((kbA1 >> 4) ^ arow[mf]) & 7) << 4));
                LDSM_X4(aH[mf][0], aH[mf][1], aH[mf][2], aH[mf][3], adH);
                LDSM_X4(aL[mf][0], aL[mf][1], aL[mf][2], aL[mf][3], adL);
            }
            #pragma unroll
            for (int p = 0; p < 2; ++p) {
                uint32_t bd = bufbase + (uint32_t)(bterm[p] + (kbB0 & ~127)
                               + ((((kbB0 >> 4) ^ brow[p]) & 7) << 4));
                LDSM_X4(bH[p][0], bH[p][1], bH[p][2], bH[p][3], bd);
            }

            // pass 1: hi*hi  (each acc written once)
            #pragma unroll
            for (int p = 0; p < 2; ++p)
                #pragma unroll
                for (int mf = 0; mf < 2; ++mf) {
                    MMA16816(acc[mf][2 * p],     aH[mf][0], aH[mf][1], aH[mf][2], aH[mf][3], bH[p][0], bH[p][1]);
                    MMA16816(acc[mf][2 * p + 1], aH[mf][0], aH[mf][1], aH[mf][2], aH[mf][3], bH[p][2], bH[p][3]);
                }
            // pass 2: lo*hi  (distance 8 from pass 1 writes)
            #pragma unroll
            for (int p = 0; p < 2; ++p)
                #pragma unroll
                for (int mf = 0; mf < 2; ++mf) {
                    MMA16816(acc[mf][2 * p],     aL[mf][0], aL[mf][1], aL[mf][2], aL[mf][3], bH[p][0], bH[p][1]);
                    MMA16816(acc[mf][2 * p + 1], aL[mf][0], aL[mf][1], aL[mf][2], aL[mf][3], bH[p][2], bH[p][3]);
                }
            // pass 3: hi*lo
            #pragma unroll
            for (int p = 0; p < 2; ++p) {
                uint32_t bL[4];
                uint32_t bd = bufbase + (uint32_t)(bterm[p] + (kbB1 & ~127)
                               + ((((kbB1 >> 4) ^ brow[p]) & 7) << 4));
                LDSM_X4(bL[0], bL[1], bL[2], bL[3], bd);
                #pragma unroll
                for (int mf = 0; mf < 2; ++mf) {
                    MMA16816(acc[mf][2 * p],     aH[mf][0], aH[mf][1], aH[mf][2], aH[mf][3], bL[0], bL[1]);
                    MMA16816(acc[mf][2 * p + 1], aH[mf][0], aH[mf][1], aH[mf][2], aH[mf][3], bL[2], bL[3]);
                }
            }
        }

        // epilogue: score + online top-3 (cols strictly ascending per thread)
        const int cb = (nt << 7) + warpN * 32 + ((lane & 3) << 1);
        #pragma unroll
        for (int nf = 0; nf < 4; ++nf) {
            #pragma unroll
            for (int j = 0; j < 2; ++j) {
                const int col = cb + nf * 8 + j;
                const float cn = smCn[col];
                #pragma unroll
                for (int mf = 0; mf < 2; ++mf) {
                    #pragma unroll
                    for (int h = 0; h < 2; ++h) {
                        const int q = mf * 2 + h;
                        float s = fmaf(-2.0f, acc[mf][nf][h * 2 + j], cn);
                        if (s < bb[q])      { bt[q] = bs[q]; bs[q] = bb[q]; is_[q] = ib[q]; bb[q] = s; ib[q] = col; }
                        else if (s < bs[q]) { bt[q] = bs[q]; bs[q] = s; is_[q] = col; }
                        else if (s < bt[q]) { bt[q] = s; }
                    }
                }
            }
        }
        __syncthreads();
    }

    // final merge: 16 candidate slots per row (4 N-warps x 4 lane-cols)
    float* exB = (float*)(sm + SM_B0);
    float* exS = exB + 2048;
    float* exT = exS + 2048;
    int*   exI = (int*)(exT + 2048);
    int*   exJ = exI + 2048;
    const int slot = (warpN << 2) + (lane & 3);
    #pragma unroll
    for (int mf = 0; mf < 2; ++mf) {
        #pragma unroll
        for (int h = 0; h < 2; ++h) {
            const int q = mf * 2 + h;
            const int r = warpM * 32 + mf * 16 + h * 8 + (lane >> 2);
            exB[r * 16 + slot] = bb[q]; exS[r * 16 + slot] = bs[q]; exT[r * 16 + slot] = bt[q];
            exI[r * 16 + slot] = ib[q]; exJ[r * 16 + slot] = is_[q];
        }
    }
    __syncthreads();
    if (tid < 128) {
        float b = 3.4e38f, s2 = 3.4e38f, t2 = 3.4e38f;
        int bi = 0x7FFFFFFF, si = 0x7FFFFFFF;
        #pragma unroll
        for (int sl = 0; sl < 16; ++sl) {
            float v0 = exB[tid * 16 + sl], v1 = exS[tid * 16 + sl], v2 = exT[tid * 16 + sl];
            int   i0 = exI[tid * 16 + sl], i1 = exJ[tid * 16 + sl];
            if (v0 < b || (v0 == b && i0 < bi)) { t2 = s2; s2 = b; si = bi; b = v0; bi = i0; }
            else if (v0 < s2 || (v0 == s2 && i0 < si)) { t2 = s2; s2 = v0; si = i0; }
            else if (v0 < t2) t2 = v0;
            if (v1 < b || (v1 == b && i1 < bi)) { t2 = s2; s2 = b; si = bi; b = v1; bi = i1; }
            else if (v1 < s2 || (v1 == s2 && i1 < si)) { t2 = s2; s2 = v1; si = i1; }
            else if (v1 < t2) t2 = v1;
            if (v2 < b) { t2 = s2; s2 = b; si = bi; b = v2; bi = 0x7FFFFFFF; }
            else if (v2 < s2) { t2 = s2; s2 = v2; si = 0x7FFFFFFF; }
            else if (v2 < t2) t2 = v2;
        }
        const int row = (blockIdx.x << 7) + tid;
        g_index[row]  = bi;
        g_index2[row] = si;
        int fl = 0;
        if (t2 <= b + MARGIN)      fl = 2;
        else if (s2 <= b + MARGIN) fl = 1;
        g_flag[row] = fl;
    }
}

// ---------------------------------------------------------------------------
// Exact rescan for flagged rows. Grid 512 x 256; block owns 128 rows.
// ---------------------------------------------------------------------------
__global__ void rescan_kernel(const float* __restrict__ x, const float* __restrict__ codes) {
    __shared__ float xs[128];
    __shared__ float rs[256];
    __shared__ int   ri[256];
    const int tid  = threadIdx.x;
    const int base = blockIdx.x << 7;
    for (int rr = 0; rr < 128; ++rr) {
        const int row = base + rr;
        const int fl = g_flag[row];
        if (fl == 0) continue;
        __syncthreads();
        if (tid < 128) xs[tid] = x[(size_t)row * DIM + tid];
        __syncthreads();
        if (fl == 1) {
            const int i0 = g_index[row], i1 = g_index2[row];
            const int c = (tid < 128) ? i0 : i1;
            const int e = tid & 127;
            rs[tid] = xs[e] * codes[(size_t)c * DIM + e];
            __syncthreads();
            #pragma unroll
            for (int st = 64; st; st >>= 1) {
                if ((tid & 127) < st) rs[tid] += rs[tid + st];
                __syncthreads();
            }
            if (tid == 0) {
                float s0 = fmaf(-2.0f, rs[0],   g_cnorm[i0]);
                float s1 = fmaf(-2.0f, rs[128], g_cnorm[i1]);
                g_index[row] = (s1 < s0 || (s1 == s0 && i1 < i0)) ? i1 : i0;
            }
            __syncthreads();
        } else {
            float b = 3.4e38f; int bi = 0;
            for (int c = tid; c < C_CODES; c += 256) {
                const float4* cp = (const float4*)(codes + (size_t)c * DIM);
                const float4* xp = (const float4*)xs;
                float dot = 0.0f;
                #pragma unroll
                for (int k = 0; k < 32; ++k) {
                    float4 cv = cp[k];
                    float4 xv = xp[k];
                    dot += xv.x * cv.x + xv.y * cv.y + xv.z * cv.z + xv.w * cv.w;
                }
                float s = fmaf(-2.0f, dot, g_cnorm[c]);
                if (s < b) { b = s; bi = c; }
            }
            rs[tid] = b; ri[tid] = bi;
            __syncthreads();
            #pragma unroll
            for (int st = 128; st; st >>= 1) {
                if (tid < st) {
                    float s2 = rs[tid + st]; int i2 = ri[tid + st];
                    if (s2 < rs[tid] || (s2 == rs[tid] && i2 < ri[tid])) { rs[tid] = s2; ri[tid] = i2; }
                }
                __syncthreads();
            }
            if (tid == 0) g_index[row] = ri[0];
            __syncthreads();
        }
    }
}

// ---------------------------------------------------------------------------
// Gather + loss
// ---------------------------------------------------------------------------
__global__ void gather_kernel(const float* __restrict__ x,
                              const float* __restrict__ codes,
                              float* __restrict__ outQ,
                              float* __restrict__ outIdx,
                              int wantIdx) {
    const int tid  = threadIdx.x;
    const int r0   = blockIdx.x << 7;
    const int half = tid >> 7;
    const int e    = tid & 127;
    float lsum = 0.0f;
    for (int it = 0; it < 64; ++it) {
        int r = r0 + (it << 1) + half;
        int idx = g_index[r];
        float cv = codes[(size_t)idx * DIM + e];
        float xv = x[(size_t)r * DIM + e];
        float d  = xv - cv;
        lsum = fmaf(d, d, lsum);
        outQ[(size_t)r * DIM + e] = cv;
        if (wantIdx && e == 0) outIdx[r] = (float)idx;
    }
    __shared__ float red[256];
    red[tid] = lsum;
    __syncthreads();
    #pragma unroll
    for (int s = 128; s > 0; s >>= 1) {
        if (tid < s) red[tid] += red[tid + s];
        __syncthreads();
    }
    if (tid == 0) g_partial[blockIdx.x] = red[0];
}

__global__ void loss_kernel(float* __restrict__ outLoss) {
    __shared__ float red[512];
    int tid = threadIdx.x;
    red[tid] = g_partial[tid];
    __syncthreads();
    #pragma unroll
    for (int s = 256; s > 0; s >>= 1) {
        if (tid < s) red[tid] += red[tid + s];
        __syncthreads();
    }
    if (tid == 0) outLoss[0] = 1.25f * red[0] / (float)B_ROWS;
}

// ---------------------------------------------------------------------------
extern "C" void kernel_launch(void* const* d_in, const int* in_sizes, int n_in,
                              void* d_out, int out_size) {
    const float* x     = (const float*)d_in[0];
    const float* codes = (const float*)d_in[1];
    float* out = (float*)d_out;

    cudaFuncSetAttribute(score_mma_kernel,
                         cudaFuncAttributeMaxDynamicSharedMemorySize, SM_TOTAL);

    split_x_kernel<<<8192, 256>>>(x);
    split_c_kernel<<<512, 256>>>(codes);
    cnorm_kernel<<<C_CODES / 8, 256>>>(codes);
    score_mma_kernel<<<B_ROWS / 128, 512, SM_TOTAL>>>();
    rescan_kernel<<<512, 256>>>(x, codes);

    long long qElems = (long long)B_ROWS * DIM;
    int wantIdx  = out_size >= (int)(qElems + B_ROWS);
    int wantLoss = out_size >= (int)(qElems + B_ROWS + 1);

    gather_kernel<<<B_ROWS / 128, 256>>>(x, codes, out, out + qElems, wantIdx);
    if (wantLoss) loss_kernel<<<1, 512>>>(out + qElems + B_ROWS);
}